// round 9
// baseline (speedup 1.0000x reference)
#include <cuda_runtime.h>
#include <cstddef>

#define N_NODES 100000
#define N_EDGES 640000
#define DIM 128
#define ALPHA 0.3f
#define BIN_CAP 64            // P(Poisson(6.4) >= 64) ~ 1e-40: safe hard bound

// ── Allocation-free scratch ─────────────────────────────────────────────
__device__ int  g_count[N_NODES];                       // cursor, then degree
__device__ int2 g_bins[(size_t)N_NODES * BIN_CAP];      // {edge_id, src} per dst bin

// K1: bin edges by dst. Cursor atomics spread over 100k addresses (avg 6.4
// per address) — near the L2 atomic-ALU spread floor.
__global__ void bin_edges(const int* __restrict__ src_idx,
                          const int* __restrict__ dst_idx) {
    int e = blockIdx.x * blockDim.x + threadIdx.x;
    if (e >= N_EDGES) return;
    int d = dst_idx[e];
    int s = src_idx[e];
    int rank = atomicAdd(&g_count[d], 1);
    g_bins[(size_t)d * BIN_CAP + rank] = make_int2(e, s);
}
// After K1, g_count[n] == degree(n).

// K2: one warp per node. Lane-parallel record fetch: ONE coalesced 8B/lane
// load grabs all <=32 {eid,src} records for the node; indices are then
// distributed via shfl (ALU, not memory), so EVERY embedding load for the
// node (~2*deg LDG.128) is independent and in flight simultaneously. This
// removes the record-load latency level from the dependent chain that held
// DRAM at 67.7% in R8.
__global__ void __launch_bounds__(256, 5)
gather_finalize(const float* __restrict__ src_emb,
                const float* __restrict__ dst_emb,
                const float* __restrict__ edge_emb,
                float*       __restrict__ out) {
    int g    = blockIdx.x * blockDim.x + threadIdx.x;
    int n    = g >> 5;
    int lane = g & 31;
    if (n >= N_NODES) return;

    int deg = g_count[n];
    const int2* bin = g_bins + (size_t)n * BIN_CAP;
    size_t off = (size_t)n * DIM + (size_t)lane * 4;

    if (deg == 0) {
        *reinterpret_cast<float4*>(out + off) = make_float4(0.f, 0.f, 0.f, 0.f);
        return;
    }

    float4 acc = make_float4(0.f, 0.f, 0.f, 0.f);
    // Independent of the gather chain: hoist to overlap.
    float4 de = __ldcs(reinterpret_cast<const float4*>(dst_emb + off));

    if (deg <= 32) {
        // One coalesced record load for the whole node.
        int2 rec = __ldg(bin + min(lane, deg - 1));

        int j = 0;
        for (; j + 3 < deg; j += 4) {
            int e0 = __shfl_sync(0xffffffffu, rec.x, j);
            int s0 = __shfl_sync(0xffffffffu, rec.y, j);
            int e1 = __shfl_sync(0xffffffffu, rec.x, j + 1);
            int s1 = __shfl_sync(0xffffffffu, rec.y, j + 1);
            int e2 = __shfl_sync(0xffffffffu, rec.x, j + 2);
            int s2 = __shfl_sync(0xffffffffu, rec.y, j + 2);
            int e3 = __shfl_sync(0xffffffffu, rec.x, j + 3);
            int s3 = __shfl_sync(0xffffffffu, rec.y, j + 3);
            float4 a0 = __ldg (reinterpret_cast<const float4*>(src_emb  + (size_t)s0 * DIM) + lane);
            float4 b0 = __ldcs(reinterpret_cast<const float4*>(edge_emb + (size_t)e0 * DIM) + lane);
            float4 a1 = __ldg (reinterpret_cast<const float4*>(src_emb  + (size_t)s1 * DIM) + lane);
            float4 b1 = __ldcs(reinterpret_cast<const float4*>(edge_emb + (size_t)e1 * DIM) + lane);
            float4 a2 = __ldg (reinterpret_cast<const float4*>(src_emb  + (size_t)s2 * DIM) + lane);
            float4 b2 = __ldcs(reinterpret_cast<const float4*>(edge_emb + (size_t)e2 * DIM) + lane);
            float4 a3 = __ldg (reinterpret_cast<const float4*>(src_emb  + (size_t)s3 * DIM) + lane);
            float4 b3 = __ldcs(reinterpret_cast<const float4*>(edge_emb + (size_t)e3 * DIM) + lane);
            acc.x += ((a0.x + b0.x) + (a1.x + b1.x)) + ((a2.x + b2.x) + (a3.x + b3.x));
            acc.y += ((a0.y + b0.y) + (a1.y + b1.y)) + ((a2.y + b2.y) + (a3.y + b3.y));
            acc.z += ((a0.z + b0.z) + (a1.z + b1.z)) + ((a2.z + b2.z) + (a3.z + b3.z));
            acc.w += ((a0.w + b0.w) + (a1.w + b1.w)) + ((a2.w + b2.w) + (a3.w + b3.w));
        }
        if (j + 1 < deg) {                 // 2-edge tail (no memory dependency: recs in regs)
            int e0 = __shfl_sync(0xffffffffu, rec.x, j);
            int s0 = __shfl_sync(0xffffffffu, rec.y, j);
            int e1 = __shfl_sync(0xffffffffu, rec.x, j + 1);
            int s1 = __shfl_sync(0xffffffffu, rec.y, j + 1);
            float4 a0 = __ldg (reinterpret_cast<const float4*>(src_emb  + (size_t)s0 * DIM) + lane);
            float4 b0 = __ldcs(reinterpret_cast<const float4*>(edge_emb + (size_t)e0 * DIM) + lane);
            float4 a1 = __ldg (reinterpret_cast<const float4*>(src_emb  + (size_t)s1 * DIM) + lane);
            float4 b1 = __ldcs(reinterpret_cast<const float4*>(edge_emb + (size_t)e1 * DIM) + lane);
            acc.x += (a0.x + b0.x) + (a1.x + b1.x);
            acc.y += (a0.y + b0.y) + (a1.y + b1.y);
            acc.z += (a0.z + b0.z) + (a1.z + b1.z);
            acc.w += (a0.w + b0.w) + (a1.w + b1.w);
            j += 2;
        }
        if (j < deg) {
            int e0 = __shfl_sync(0xffffffffu, rec.x, j);
            int s0 = __shfl_sync(0xffffffffu, rec.y, j);
            float4 a0 = __ldg (reinterpret_cast<const float4*>(src_emb  + (size_t)s0 * DIM) + lane);
            float4 b0 = __ldcs(reinterpret_cast<const float4*>(edge_emb + (size_t)e0 * DIM) + lane);
            acc.x += a0.x + b0.x;
            acc.y += a0.y + b0.y;
            acc.z += a0.z + b0.z;
            acc.w += a0.w + b0.w;
        }
    } else {
        // deg > 32: astronomically rare — generic path for correctness.
        for (int j = 0; j < deg; j++) {
            int2 r0 = __ldg(bin + j);
            float4 a0 = __ldg (reinterpret_cast<const float4*>(src_emb  + (size_t)r0.y * DIM) + lane);
            float4 b0 = __ldcs(reinterpret_cast<const float4*>(edge_emb + (size_t)r0.x * DIM) + lane);
            acc.x += a0.x + b0.x;
            acc.y += a0.y + b0.y;
            acc.z += a0.z + b0.z;
            acc.w += a0.w + b0.w;
        }
    }

    float inv = (1.0f - ALPHA) / (float)deg;
    float4 r;
    r.x = ALPHA * de.x + acc.x * inv;
    r.y = ALPHA * de.y + acc.y * inv;
    r.z = ALPHA * de.z + acc.z * inv;
    r.w = ALPHA * de.w + acc.w * inv;
    *reinterpret_cast<float4*>(out + off) = r;
}

extern "C" void kernel_launch(void* const* d_in, const int* in_sizes, int n_in,
                              void* d_out, int out_size) {
    const float* src_emb  = (const float*)d_in[0];
    const float* dst_emb  = (const float*)d_in[1];
    const float* edge_emb = (const float*)d_in[2];
    const int*   src_idx  = (const int*)d_in[3];
    const int*   dst_idx  = (const int*)d_in[4];
    float* out = (float*)d_out;

    int* d_count;
    cudaGetSymbolAddress((void**)&d_count, g_count);
    cudaMemsetAsync(d_count, 0, N_NODES * sizeof(int));    // graph-legal, no launch

    bin_edges<<<(N_EDGES + 255) / 256, 256>>>(src_idx, dst_idx);

    {
        long long total = (long long)N_NODES * 32;   // one warp per node
        int blocks = (int)((total + 255) / 256);
        gather_finalize<<<blocks, 256>>>(src_emb, dst_emb, edge_emb, out);
    }
}